// round 1
// baseline (speedup 1.0000x reference)
#include <cuda_runtime.h>

// YOLO-style detection loss.
// preds:  (n, L*(C+5B)) = (n, 1470) f32   [pcls 980 | pconf 98 | pbox 392]
// labels: (n, L*(1+C+4)) = (n, 1225) f32  per cell: [flag | 20 cls | 4 box]
// out: scalar f32 (sum of conf + cls + coord deltas)

#define S_GRID 7
#define L_CELLS 49
#define C_CLS 20
#define ROW_P 1470
#define ROW_L 1225
#define NOOBJ_W 0.5f
#define OBJ_W 0.5f
#define CLS_W 0.5f
#define COORD_W 2.5f

__device__ double g_acc;

__global__ void zero_acc_kernel() { g_acc = 0.0; }

__global__ void finalize_kernel(float* out) { out[0] = (float)g_acc; }

__global__ void __launch_bounds__(256) yolo_loss_kernel(
    const float* __restrict__ preds,
    const float* __restrict__ labels,
    int total_cells)
{
    int idx = blockIdx.x * blockDim.x + threadIdx.x;
    float v = 0.0f;

    if (idx < total_cells) {
        int i = idx / L_CELLS;
        int l = idx - i * L_CELLS;

        const float* p  = preds  + (size_t)i * ROW_P;
        const float* lb = labels + (size_t)i * ROW_L + l * 25;

        float flag = __ldg(lb);
        // pconf: offset 980 + 2l within row; base parity even -> 8B aligned
        float2 pc = *reinterpret_cast<const float2*>(p + 980 + l * 2);

        if (flag == 0.0f) {
            // no-object cell: only NOOBJ confidence penalty on both boxes
            v = NOOBJ_W * (pc.x * pc.x + pc.y * pc.y);
        } else {
            // ---- load target box ----
            float tb0 = __ldg(lb + 21);
            float tb1 = __ldg(lb + 22);
            float tb2 = __ldg(lb + 23);
            float tb3 = __ldg(lb + 24);

            // ---- load predicted boxes (8 floats, 8B aligned) ----
            const float* pb = p + 1078 + l * 8;
            float2 b01 = *reinterpret_cast<const float2*>(pb + 0);
            float2 b23 = *reinterpret_cast<const float2*>(pb + 2);
            float2 b45 = *reinterpret_cast<const float2*>(pb + 4);
            float2 b67 = *reinterpret_cast<const float2*>(pb + 6);

            // transformed boxes: o = [x/S, y/S, w^2, h^2]
            float o0x = b01.x / 7.0f, o0y = b01.y / 7.0f;
            float o0w = b23.x * b23.x, o0h = b23.y * b23.y;
            float o1x = b45.x / 7.0f, o1y = b45.y / 7.0f;
            float o1w = b67.x * b67.x, o1h = b67.y * b67.y;

            // target: t = [x/S, y/S, w, h]
            float tx = tb0 / 7.0f, ty = tb1 / 7.0f, tw = tb2, th = tb3;

            // ---- IoU for both boxes ----
            float iou0, iou1, r0, r1;
            {
                float left   = fmaxf(tx - 0.5f * tw, o0x - 0.5f * o0w);
                float right  = fminf(tx + 0.5f * tw, o0x + 0.5f * o0w);
                float top    = fmaxf(ty - 0.5f * th, o0y - 0.5f * o0h);
                float bottom = fminf(ty + 0.5f * th, o0y + 0.5f * o0h);
                float w = right - left, h = bottom - top;
                bool invalid = (w < 0.0f) || (h < 0.0f);
                float inter = invalid ? 0.0f : w * h;
                float uni = tw * th + o0w * o0h - inter;
                iou0 = invalid ? 0.0f : inter / fmaxf(uni, 1e-12f);
                float d0 = tx - o0x, d1 = ty - o0y, d2 = tw - o0w, d3 = th - o0h;
                r0 = d0 * d0 + d1 * d1 + d2 * d2 + d3 * d3;
            }
            {
                float left   = fmaxf(tx - 0.5f * tw, o1x - 0.5f * o1w);
                float right  = fminf(tx + 0.5f * tw, o1x + 0.5f * o1w);
                float top    = fmaxf(ty - 0.5f * th, o1y - 0.5f * o1h);
                float bottom = fminf(ty + 0.5f * th, o1y + 0.5f * o1h);
                float w = right - left, h = bottom - top;
                bool invalid = (w < 0.0f) || (h < 0.0f);
                float inter = invalid ? 0.0f : w * h;
                float uni = tw * th + o1w * o1h - inter;
                iou1 = invalid ? 0.0f : inter / fmaxf(uni, 1e-12f);
                float d0 = tx - o1x, d1 = ty - o1y, d2 = tw - o1w, d3 = th - o1h;
                r1 = d0 * d0 + d1 * d1 + d2 * d2 + d3 * d3;
            }

            // ---- best box selection (argmax first-index semantics) ----
            float miou = fmaxf(iou0, iou1);
            int best;
            if (miou > 0.0f) best = (iou1 > iou0) ? 1 : 0;
            else             best = (r1 < r0) ? 1 : 0;

            float best_iou  = best ? iou1 : iou0;
            float conf_best = best ? pc.y : pc.x;
            float conf_oth  = best ? pc.x : pc.y;
            float dcb = best_iou - conf_best;
            float conf = OBJ_W * dcb * dcb + NOOBJ_W * conf_oth * conf_oth;

            // ---- class loss (20 classes) ----
            const float* pcl = p + l * 20;  // 8B aligned
            float cls = 0.0f;
            #pragma unroll
            for (int c = 0; c < 20; c += 2) {
                float2 pv = *reinterpret_cast<const float2*>(pcl + c);
                float d0 = __ldg(lb + 1 + c)     - pv.x;
                float d1 = __ldg(lb + 1 + c + 1) - pv.y;
                cls += d0 * d0 + d1 * d1;
            }
            cls *= CLS_W;

            // ---- coordinate loss on best raw box ----
            float pbx = best ? b45.x : b01.x;
            float pby = best ? b45.y : b01.y;
            float pbw = best ? b67.x : b23.x;
            float pbh = best ? b67.y : b23.y;
            float st2 = sqrtf(tb2), st3 = sqrtf(tb3);
            float e0 = tb0 - pbx, e1 = tb1 - pby;
            float e2 = st2 - pbw, e3 = st3 - pbh;
            float coord = COORD_W * (e0 * e0 + e1 * e1 + e2 * e2 + e3 * e3);

            v = conf + cls + coord;
        }
    }

    // ---- reduction: warp shuffle -> shared -> one atomic per block ----
    double s = (double)v;
    #pragma unroll
    for (int off = 16; off > 0; off >>= 1)
        s += __shfl_down_sync(0xffffffffu, s, off);

    __shared__ double warp_sums[8];
    int lane = threadIdx.x & 31;
    int wid  = threadIdx.x >> 5;
    if (lane == 0) warp_sums[wid] = s;
    __syncthreads();

    if (wid == 0) {
        double t = (lane < 8) ? warp_sums[lane] : 0.0;
        #pragma unroll
        for (int off = 4; off > 0; off >>= 1)
            t += __shfl_down_sync(0xffffffffu, t, off);
        if (lane == 0) atomicAdd(&g_acc, t);
    }
}

extern "C" void kernel_launch(void* const* d_in, const int* in_sizes, int n_in,
                              void* d_out, int out_size)
{
    const float* preds  = (const float*)d_in[0];
    const float* labels = (const float*)d_in[1];
    int n = in_sizes[0] / ROW_P;
    int total_cells = n * L_CELLS;
    int threads = 256;
    int blocks = (total_cells + threads - 1) / threads;

    zero_acc_kernel<<<1, 1>>>();
    yolo_loss_kernel<<<blocks, threads>>>(preds, labels, total_cells);
    finalize_kernel<<<1, 1>>>((float*)d_out);
}

// round 3
// speedup vs baseline: 1.1574x; 1.1574x over previous
#include <cuda_runtime.h>

// YOLO-style detection loss.
// preds:  (n, 1470) f32  [pcls 980 | pconf 98 | pbox 392]
// labels: (n, 1225) f32  per cell (25 floats): [flag | 20 cls | 4 box]
// NOTE: row strides 1470/1225 floats => row bases are only 8B-aligned for
// odd rows. All vector loads must be float2 (8B), never float4.

#define L_CELLS 49
#define ROW_P 1470
#define ROW_L 1225
#define NOOBJ_W 0.5f
#define OBJ_W 0.5f
#define CLS_W 0.5f
#define COORD_W 2.5f

#define THREADS 256
#define CPT 4          // cells per thread
#define MAX_BLOCKS 4096

__device__ double g_partials[MAX_BLOCKS];

__device__ __forceinline__ float obj_cell_loss(
    const float* __restrict__ p, const float* __restrict__ lb,
    int l, float pcx, float pcy)
{
    // ---- target box ----
    float tb0 = __ldg(lb + 21);
    float tb1 = __ldg(lb + 22);
    float tb2 = __ldg(lb + 23);
    float tb3 = __ldg(lb + 24);

    // ---- predicted boxes (8 floats; 8B aligned: 1078 + 8l, row base even) ----
    const float* pb = p + 1078 + l * 8;
    float2 b01 = __ldg(reinterpret_cast<const float2*>(pb + 0));
    float2 b23 = __ldg(reinterpret_cast<const float2*>(pb + 2));
    float2 b45 = __ldg(reinterpret_cast<const float2*>(pb + 4));
    float2 b67 = __ldg(reinterpret_cast<const float2*>(pb + 6));

    // ---- class loss (float2 only: base offset l*20 is even -> 8B aligned) ----
    const float* pcl = p + l * 20;
    float cls = 0.0f;
    #pragma unroll
    for (int c = 0; c < 20; c += 2) {
        float2 pv = __ldg(reinterpret_cast<const float2*>(pcl + c));
        float d0 = __ldg(lb + 1 + c)     - pv.x;
        float d1 = __ldg(lb + 2 + c)     - pv.y;
        cls += d0 * d0 + d1 * d1;
    }
    cls *= CLS_W;

    // transformed boxes: o = [x/S, y/S, w^2, h^2]; t = [x/S, y/S, w, h]
    float o0x = b01.x * (1.0f / 7.0f), o0y = b01.y * (1.0f / 7.0f);
    float o0w = b23.x * b23.x,         o0h = b23.y * b23.y;
    float o1x = b45.x * (1.0f / 7.0f), o1y = b45.y * (1.0f / 7.0f);
    float o1w = b67.x * b67.x,         o1h = b67.y * b67.y;
    float tx = tb0 * (1.0f / 7.0f), ty = tb1 * (1.0f / 7.0f);
    float tw = tb2, th = tb3;

    // ---- IoU + rmse^2 for both boxes ----
    float iou0, iou1, r0, r1;
    {
        float left   = fmaxf(tx - 0.5f * tw, o0x - 0.5f * o0w);
        float right  = fminf(tx + 0.5f * tw, o0x + 0.5f * o0w);
        float top    = fmaxf(ty - 0.5f * th, o0y - 0.5f * o0h);
        float bottom = fminf(ty + 0.5f * th, o0y + 0.5f * o0h);
        float w = right - left, h = bottom - top;
        bool invalid = (w < 0.0f) || (h < 0.0f);
        float inter = invalid ? 0.0f : w * h;
        float uni = tw * th + o0w * o0h - inter;
        iou0 = invalid ? 0.0f : inter / fmaxf(uni, 1e-12f);
        float d0 = tx - o0x, d1 = ty - o0y, d2 = tw - o0w, d3 = th - o0h;
        r0 = d0 * d0 + d1 * d1 + d2 * d2 + d3 * d3;
    }
    {
        float left   = fmaxf(tx - 0.5f * tw, o1x - 0.5f * o1w);
        float right  = fminf(tx + 0.5f * tw, o1x + 0.5f * o1w);
        float top    = fmaxf(ty - 0.5f * th, o1y - 0.5f * o1h);
        float bottom = fminf(ty + 0.5f * th, o1y + 0.5f * o1h);
        float w = right - left, h = bottom - top;
        bool invalid = (w < 0.0f) || (h < 0.0f);
        float inter = invalid ? 0.0f : w * h;
        float uni = tw * th + o1w * o1h - inter;
        iou1 = invalid ? 0.0f : inter / fmaxf(uni, 1e-12f);
        float d0 = tx - o1x, d1 = ty - o1y, d2 = tw - o1w, d3 = th - o1h;
        r1 = d0 * d0 + d1 * d1 + d2 * d2 + d3 * d3;
    }

    // ---- best box (argmax/argmin first-index tie semantics) ----
    float miou = fmaxf(iou0, iou1);
    int best = (miou > 0.0f) ? ((iou1 > iou0) ? 1 : 0)
                             : ((r1 < r0) ? 1 : 0);

    float best_iou  = best ? iou1 : iou0;
    float conf_best = best ? pcy : pcx;
    float dcb = best_iou - conf_best;
    // correction vs the unconditional NOOBJ*(pcx^2+pcy^2) base term
    float conf_corr = OBJ_W * dcb * dcb - NOOBJ_W * conf_best * conf_best;

    // ---- coordinate loss on best raw box ----
    float pbx = best ? b45.x : b01.x;
    float pby = best ? b45.y : b01.y;
    float pbw = best ? b67.x : b23.x;
    float pbh = best ? b67.y : b23.y;
    float st2 = sqrtf(tb2), st3 = sqrtf(tb3);
    float e0 = tb0 - pbx, e1 = tb1 - pby;
    float e2 = st2 - pbw, e3 = st3 - pbh;
    float coord = COORD_W * (e0 * e0 + e1 * e1 + e2 * e2 + e3 * e3);

    return conf_corr + cls + coord;
}

__global__ void __launch_bounds__(THREADS) yolo_loss_kernel(
    const float* __restrict__ preds,
    const float* __restrict__ labels,
    int total_cells)
{
    const int t = blockIdx.x * blockDim.x + threadIdx.x;
    const int stride = gridDim.x * blockDim.x;

    // ---- phase 1: issue all mandatory loads (flags + pconf), MLP = 8 ----
    int   ii[CPT], ll[CPT];
    float flag[CPT];
    float2 pc[CPT];
    bool  valid[CPT];

    #pragma unroll
    for (int k = 0; k < CPT; k++) {
        int cell = t + k * stride;
        valid[k] = cell < total_cells;
        int c = valid[k] ? cell : 0;
        ii[k] = c / L_CELLS;
        ll[k] = c - ii[k] * L_CELLS;
    }
    #pragma unroll
    for (int k = 0; k < CPT; k++) {
        flag[k] = __ldg(labels + (size_t)ii[k] * ROW_L + ll[k] * 25);
        pc[k] = __ldg(reinterpret_cast<const float2*>(
                      preds + (size_t)ii[k] * ROW_P + 980 + ll[k] * 2));
    }

    // ---- phase 2: accumulate ----
    float v = 0.0f;
    #pragma unroll
    for (int k = 0; k < CPT; k++) {
        if (!valid[k]) continue;
        // unconditional noobj base on both confidences
        v += NOOBJ_W * (pc[k].x * pc[k].x + pc[k].y * pc[k].y);
        if (flag[k] != 0.0f) {
            const float* p  = preds  + (size_t)ii[k] * ROW_P;
            const float* lb = labels + (size_t)ii[k] * ROW_L + ll[k] * 25;
            v += obj_cell_loss(p, lb, ll[k], pc[k].x, pc[k].y);
        }
    }

    // ---- block reduction to a single double partial ----
    double s = (double)v;
    #pragma unroll
    for (int off = 16; off > 0; off >>= 1)
        s += __shfl_down_sync(0xffffffffu, s, off);

    __shared__ double warp_sums[THREADS / 32];
    int lane = threadIdx.x & 31;
    int wid  = threadIdx.x >> 5;
    if (lane == 0) warp_sums[wid] = s;
    __syncthreads();

    if (wid == 0) {
        double x = (lane < THREADS / 32) ? warp_sums[lane] : 0.0;
        #pragma unroll
        for (int off = 4; off > 0; off >>= 1)
            x += __shfl_down_sync(0xffffffffu, x, off);
        if (lane == 0) g_partials[blockIdx.x] = x;
    }
}

__global__ void __launch_bounds__(256) finalize_kernel(float* out, int nblocks)
{
    double s = 0.0;
    for (int i = threadIdx.x; i < nblocks; i += 256)
        s += g_partials[i];

    #pragma unroll
    for (int off = 16; off > 0; off >>= 1)
        s += __shfl_down_sync(0xffffffffu, s, off);

    __shared__ double warp_sums[8];
    int lane = threadIdx.x & 31;
    int wid  = threadIdx.x >> 5;
    if (lane == 0) warp_sums[wid] = s;
    __syncthreads();

    if (wid == 0) {
        double x = (lane < 8) ? warp_sums[lane] : 0.0;
        #pragma unroll
        for (int off = 4; off > 0; off >>= 1)
            x += __shfl_down_sync(0xffffffffu, x, off);
        if (lane == 0) out[0] = (float)x;
    }
}

extern "C" void kernel_launch(void* const* d_in, const int* in_sizes, int n_in,
                              void* d_out, int out_size)
{
    const float* preds  = (const float*)d_in[0];
    const float* labels = (const float*)d_in[1];
    int n = in_sizes[0] / ROW_P;
    int total_cells = n * L_CELLS;

    int blocks = (total_cells + THREADS * CPT - 1) / (THREADS * CPT);
    if (blocks > MAX_BLOCKS) blocks = MAX_BLOCKS;

    yolo_loss_kernel<<<blocks, THREADS>>>(preds, labels, total_cells);
    finalize_kernel<<<1, 256>>>((float*)d_out, blocks);
}

// round 4
// speedup vs baseline: 1.4949x; 1.2917x over previous
#include <cuda_runtime.h>

// YOLO-style detection loss.
// preds:  (n, 1470) f32  [pcls 980 | pconf 98 | pbox 392]
// labels: (n, 1225) f32  per cell (25 floats): [flag | 20 cls | 4 box]
// Row strides 1470/1225 floats => row bases only 8B-aligned for odd rows.
// All vector loads must be float2 (8B), never float4.

#define L_CELLS 49
#define ROW_P 1470
#define ROW_L 1225
#define NOOBJ_W 0.5f
#define OBJ_W 0.5f
#define CLS_W 0.5f
#define COORD_W 2.5f

#define THREADS 256
#define CPT 4                         // cells per thread (phase 1)
#define CELLS_PER_BLOCK (THREADS * CPT)
#define NWARPS (THREADS / 32)
#define MAX_BLOCKS 8192

__device__ double   g_partials[MAX_BLOCKS];
__device__ unsigned g_counter = 0;    // self-wrapping; replay-safe

__device__ __forceinline__ float obj_cell_loss(
    const float* __restrict__ preds,
    const float* __restrict__ labels,
    int i, int l)
{
    const float* p  = preds  + (size_t)i * ROW_P;
    const float* lb = labels + (size_t)i * ROW_L + l * 25;

    // ---- issue all loads up front ----
    float2 pc = __ldg(reinterpret_cast<const float2*>(p + 980 + l * 2));

    float tb0 = __ldg(lb + 21);
    float tb1 = __ldg(lb + 22);
    float tb2 = __ldg(lb + 23);
    float tb3 = __ldg(lb + 24);

    const float* pb = p + 1078 + l * 8;       // 8B aligned
    float2 b01 = __ldg(reinterpret_cast<const float2*>(pb + 0));
    float2 b23 = __ldg(reinterpret_cast<const float2*>(pb + 2));
    float2 b45 = __ldg(reinterpret_cast<const float2*>(pb + 4));
    float2 b67 = __ldg(reinterpret_cast<const float2*>(pb + 6));

    // ---- class loss (float2 only; l*20 even -> 8B aligned) ----
    const float* pcl = p + l * 20;
    float cls = 0.0f;
    #pragma unroll
    for (int c = 0; c < 20; c += 2) {
        float2 pv = __ldg(reinterpret_cast<const float2*>(pcl + c));
        float d0 = __ldg(lb + 1 + c) - pv.x;
        float d1 = __ldg(lb + 2 + c) - pv.y;
        cls += d0 * d0 + d1 * d1;
    }
    cls *= CLS_W;

    // transformed: o = [x/S, y/S, w^2, h^2]; t = [x/S, y/S, w, h]
    float o0x = b01.x * (1.0f / 7.0f), o0y = b01.y * (1.0f / 7.0f);
    float o0w = b23.x * b23.x,         o0h = b23.y * b23.y;
    float o1x = b45.x * (1.0f / 7.0f), o1y = b45.y * (1.0f / 7.0f);
    float o1w = b67.x * b67.x,         o1h = b67.y * b67.y;
    float tx = tb0 * (1.0f / 7.0f), ty = tb1 * (1.0f / 7.0f);
    float tw = tb2, th = tb3;

    float iou0, iou1, r0, r1;
    {
        float left   = fmaxf(tx - 0.5f * tw, o0x - 0.5f * o0w);
        float right  = fminf(tx + 0.5f * tw, o0x + 0.5f * o0w);
        float top    = fmaxf(ty - 0.5f * th, o0y - 0.5f * o0h);
        float bottom = fminf(ty + 0.5f * th, o0y + 0.5f * o0h);
        float w = right - left, h = bottom - top;
        bool invalid = (w < 0.0f) || (h < 0.0f);
        float inter = invalid ? 0.0f : w * h;
        float uni = tw * th + o0w * o0h - inter;
        iou0 = invalid ? 0.0f : inter / fmaxf(uni, 1e-12f);
        float d0 = tx - o0x, d1 = ty - o0y, d2 = tw - o0w, d3 = th - o0h;
        r0 = d0 * d0 + d1 * d1 + d2 * d2 + d3 * d3;
    }
    {
        float left   = fmaxf(tx - 0.5f * tw, o1x - 0.5f * o1w);
        float right  = fminf(tx + 0.5f * tw, o1x + 0.5f * o1w);
        float top    = fmaxf(ty - 0.5f * th, o1y - 0.5f * o1h);
        float bottom = fminf(ty + 0.5f * th, o1y + 0.5f * o1h);
        float w = right - left, h = bottom - top;
        bool invalid = (w < 0.0f) || (h < 0.0f);
        float inter = invalid ? 0.0f : w * h;
        float uni = tw * th + o1w * o1h - inter;
        iou1 = invalid ? 0.0f : inter / fmaxf(uni, 1e-12f);
        float d0 = tx - o1x, d1 = ty - o1y, d2 = tw - o1w, d3 = th - o1h;
        r1 = d0 * d0 + d1 * d1 + d2 * d2 + d3 * d3;
    }

    // argmax/argmin first-index tie semantics
    float miou = fmaxf(iou0, iou1);
    int best = (miou > 0.0f) ? ((iou1 > iou0) ? 1 : 0)
                             : ((r1 < r0) ? 1 : 0);

    float best_iou  = best ? iou1 : iou0;
    float conf_best = best ? pc.y : pc.x;
    float dcb = best_iou - conf_best;
    // correction vs unconditional NOOBJ*(cx^2+cy^2) base added in phase 1
    float conf_corr = OBJ_W * dcb * dcb - NOOBJ_W * conf_best * conf_best;

    float pbx = best ? b45.x : b01.x;
    float pby = best ? b45.y : b01.y;
    float pbw = best ? b67.x : b23.x;
    float pbh = best ? b67.y : b23.y;
    float st2 = sqrtf(tb2), st3 = sqrtf(tb3);
    float e0 = tb0 - pbx, e1 = tb1 - pby;
    float e2 = st2 - pbw, e3 = st3 - pbh;
    float coord = COORD_W * (e0 * e0 + e1 * e1 + e2 * e2 + e3 * e3);

    return conf_corr + cls + coord;
}

__global__ void __launch_bounds__(THREADS) yolo_loss_kernel(
    const float* __restrict__ preds,
    const float* __restrict__ labels,
    int total_cells,
    float* __restrict__ out)
{
    __shared__ int    s_idx[CELLS_PER_BLOCK];   // compacted obj cell local ids
    __shared__ int    s_wcnt[NWARPS];
    __shared__ double s_red[NWARPS];

    const int tid  = threadIdx.x;
    const int lane = tid & 31;
    const int wid  = tid >> 5;
    const int base = blockIdx.x * CELLS_PER_BLOCK;
    const unsigned lmask = (1u << lane) - 1u;

    // ================= phase 1: flags + pconf, coalesced, MLP=8 =============
    float  flag[CPT];
    float2 pc[CPT];
    bool   valid[CPT];
    int    ii[CPT], ll[CPT];

    #pragma unroll
    for (int k = 0; k < CPT; k++) {
        int cell = base + k * THREADS + tid;
        valid[k] = cell < total_cells;
        int c = valid[k] ? cell : 0;
        ii[k] = c / L_CELLS;
        ll[k] = c - ii[k] * L_CELLS;
    }
    #pragma unroll
    for (int k = 0; k < CPT; k++) {
        flag[k] = __ldg(labels + (size_t)ii[k] * ROW_L + ll[k] * 25);
        pc[k]   = __ldg(reinterpret_cast<const float2*>(
                        preds + (size_t)ii[k] * ROW_P + 980 + ll[k] * 2));
    }

    float vbase = 0.0f;
    unsigned bal[CPT];
    int wcnt = 0;
    #pragma unroll
    for (int k = 0; k < CPT; k++) {
        if (valid[k])
            vbase += NOOBJ_W * (pc[k].x * pc[k].x + pc[k].y * pc[k].y);
        bool o = valid[k] && (flag[k] != 0.0f);
        bal[k] = __ballot_sync(0xffffffffu, o);
        wcnt += __popc(bal[k]);
    }
    if (lane == 0) s_wcnt[wid] = wcnt;
    __syncthreads();

    // deterministic warp-offset scan + total
    int woff = 0, total_obj = 0;
    #pragma unroll
    for (int w = 0; w < NWARPS; w++) {
        int c = s_wcnt[w];
        if (w < wid) woff += c;
        total_obj += c;
    }

    // write compacted indices (deterministic positions)
    int p = woff;
    #pragma unroll
    for (int k = 0; k < CPT; k++) {
        bool o = valid[k] && (flag[k] != 0.0f);
        int pos = p + __popc(bal[k] & lmask);
        if (o) s_idx[pos] = k * THREADS + tid;
        p += __popc(bal[k]);
    }
    __syncthreads();

    // ================= phase 2: dense obj processing =========================
    double vd = (double)vbase;
    for (int t = tid; t < total_obj; t += THREADS) {
        int cell = base + s_idx[t];
        int i = cell / L_CELLS;
        int l = cell - i * L_CELLS;
        vd += (double)obj_cell_loss(preds, labels, i, l);
    }

    // ================= block reduction (fixed tree, deterministic) ==========
    #pragma unroll
    for (int off = 16; off > 0; off >>= 1)
        vd += __shfl_down_sync(0xffffffffu, vd, off);
    if (lane == 0) s_red[wid] = vd;
    __syncthreads();

    if (wid == 0) {
        double x = (lane < NWARPS) ? s_red[lane] : 0.0;
        #pragma unroll
        for (int off = 4; off > 0; off >>= 1)
            x += __shfl_down_sync(0xffffffffu, x, off);
        if (lane == 0) g_partials[blockIdx.x] = x;
    }
    __syncthreads();

    // ================= fused finalize: last block reduces partials ==========
    __shared__ bool s_last;
    if (tid == 0) {
        __threadfence();
        unsigned old = atomicInc(&g_counter, gridDim.x - 1);
        s_last = (old == gridDim.x - 1);
    }
    __syncthreads();

    if (s_last) {
        __threadfence();
        double s = 0.0;
        for (int i = tid; i < gridDim.x; i += THREADS)
            s += g_partials[i];
        #pragma unroll
        for (int off = 16; off > 0; off >>= 1)
            s += __shfl_down_sync(0xffffffffu, s, off);
        if (lane == 0) s_red[wid] = s;
        __syncthreads();
        if (wid == 0) {
            double x = (lane < NWARPS) ? s_red[lane] : 0.0;
            #pragma unroll
            for (int off = 4; off > 0; off >>= 1)
                x += __shfl_down_sync(0xffffffffu, x, off);
            if (lane == 0) out[0] = (float)x;
        }
    }
}

extern "C" void kernel_launch(void* const* d_in, const int* in_sizes, int n_in,
                              void* d_out, int out_size)
{
    const float* preds  = (const float*)d_in[0];
    const float* labels = (const float*)d_in[1];
    int n = in_sizes[0] / ROW_P;
    int total_cells = n * L_CELLS;

    int blocks = (total_cells + CELLS_PER_BLOCK - 1) / CELLS_PER_BLOCK;
    if (blocks > MAX_BLOCKS) blocks = MAX_BLOCKS;   // n=16384 -> 784 blocks

    yolo_loss_kernel<<<blocks, THREADS>>>(preds, labels, total_cells,
                                          (float*)d_out);
}